// round 14
// baseline (speedup 1.0000x reference)
#include <cuda_runtime.h>
#include <cuda_fp16.h>
#include <cstdint>
#include <math.h>

#define DD 128
#define PP 512
#define WC 640
#define NN 131072
#define MARGIN 0.5f

// ---------------- device scratch ----------------
__device__ __align__(16) float  g_cbT[DD*PP];
__device__ __align__(16) float  g_mean[DD];
__device__ __align__(16) float  g_cov[DD*DD];
__device__ __align__(16) double g_NX[2][DD*DD];
__device__ __align__(16) float  g_Sf[DD*DD];
__device__ __align__(16) float  g_W[DD*WC];             // k-major W (rescore)
__device__ __align__(16) unsigned short g_Wh[WC*DD];    // j-major hi fp16
__device__ __align__(16) float  g_cq[PP];
__device__ int    g_counts[PP];
__device__ double g_blocksum[128];
__device__ int    g_idx[NN];
__device__ float  g_bestv[NN];
__device__ int    g_flags[NN];
__device__ int    g_nflag;
__device__ int    g_done;

// ---------------- helpers ----------------
__device__ __forceinline__ uint32_t smem_u32(const void* p) {
    uint32_t a;
    asm("{ .reg .u64 t; cvta.to.shared.u64 t, %1; cvt.u32.u64 %0, t; }" : "=r"(a) : "l"(p));
    return a;
}
__device__ __forceinline__ void cp16(uint32_t dst, const void* src) {
    asm volatile("cp.async.cg.shared.global [%0], [%1], 16;" :: "r"(dst), "l"(src));
}
#define CP_COMMIT() asm volatile("cp.async.commit_group;" ::: "memory")
#define CP_WAIT0()  asm volatile("cp.async.wait_group 0;" ::: "memory")
#define CP_WAIT1()  asm volatile("cp.async.wait_group 1;" ::: "memory")

__device__ __forceinline__ void ldsm4(uint32_t& r0, uint32_t& r1, uint32_t& r2, uint32_t& r3, uint32_t a) {
    asm volatile("ldmatrix.sync.aligned.m8n8.x4.shared.b16 {%0,%1,%2,%3}, [%4];"
        : "=r"(r0), "=r"(r1), "=r"(r2), "=r"(r3) : "r"(a) : "memory");
}
__device__ __forceinline__ void mma_h16(uint32_t* c, const uint32_t* a, uint32_t b0, uint32_t b1) {
    asm volatile("mma.sync.aligned.m16n8k16.row.col.f16.f16.f16.f16 "
        "{%0,%1}, {%2,%3,%4,%5}, {%6,%7}, {%0,%1};"
        : "+r"(c[0]), "+r"(c[1])
        : "r"(a[0]), "r"(a[1]), "r"(a[2]), "r"(a[3]), "r"(b0), "r"(b1));
}

// ---------------- precompute ----------------
// transpose + mean + state reset
__global__ void k_transmean(const float* __restrict__ cb) {   // <<<128, 256>>>
    __shared__ float sh[256];
    int j = blockIdx.x, t = threadIdx.x;
    float a = cb[t*DD + j], b = cb[(t + 256)*DD + j];
    g_cbT[j*PP + t] = a;
    g_cbT[j*PP + t + 256] = b;
    sh[t] = a + b;
    __syncthreads();
    for (int o = 128; o; o >>= 1) { if (t < o) sh[t] += sh[t+o]; __syncthreads(); }
    if (t == 0) g_mean[j] = sh[0] * (1.0f / (float)PP);
    if (j < 2) g_counts[j*256 + t] = 0;
    if (j == 0 && t == 0) { g_nflag = 0; g_done = 0; }
}
// cov + NS init (UNCHANGED per-output fp32 arithmetic: tie-structure sensitive)
__global__ void k_cov() {                          // <<<2048, 256>>>
    int w = (blockIdx.x*blockDim.x + threadIdx.x) >> 5;
    int lane = threadIdx.x & 31;
    int i = w >> 7, j = w & 127;
    float mi = g_mean[i], mj = g_mean[j];
    float s = 0.f;
    for (int p = lane; p < PP; p += 32)
        s = fmaf(g_cbT[i*PP+p]-mi, g_cbT[j*PP+p]-mj, s);
    #pragma unroll
    for (int o = 16; o; o >>= 1) s += __shfl_xor_sync(0xffffffffu, s, o);
    if (lane == 0) {
        s = s / (float)(PP - 1);
        if (i == j) s += 1e-3f;
        g_cov[i*DD+j] = s;
        g_NX[0][i*DD+j] = (i == j) ? 1.0 / (double)s : 0.0;
    }
}
// ONE fused Newton-Schulz iteration: block owns 4 output rows; U block-local.
// Symmetric reads (cov, X) keep all global accesses coalesced.
__global__ void __launch_bounds__(256) k_ns(int sel, int emit) {   // <<<32, 256>>>
    __shared__ double Xs[4][DD];
    __shared__ double Us[4][DD];
    const double* Xn = g_NX[sel];
    int tid = threadIdx.x;
    int j = tid & 127, io = tid >> 7;          // io 0..1
    int i0 = blockIdx.x * 4;

    for (int r = tid; r < 4*DD; r += 256)
        Xs[r >> 7][r & 127] = Xn[(i0 + (r >> 7))*DD + (r & 127)];
    __syncthreads();

    // U[i][j] = sum_k X[i][k] * cov[j][k]  (cov symmetric -> cov[k*DD+j] coalesced)
    for (int rr = io; rr < 4; rr += 2) {
        double s0 = 0.0, s1 = 0.0, s2 = 0.0, s3 = 0.0;
        for (int k = 0; k < DD; k += 4) {
            s0 += Xs[rr][k+0] * (double)g_cov[(k+0)*DD + j];
            s1 += Xs[rr][k+1] * (double)g_cov[(k+1)*DD + j];
            s2 += Xs[rr][k+2] * (double)g_cov[(k+2)*DD + j];
            s3 += Xs[rr][k+3] * (double)g_cov[(k+3)*DD + j];
        }
        Us[rr][j] = (s0 + s1) + (s2 + s3);
    }
    __syncthreads();

    // X'[i][j] = 2X[i][j] - sum_k U[i][k] * X[j][k]  (X symmetric -> Xn[k*DD+j])
    for (int rr = io; rr < 4; rr += 2) {
        double s0 = 0.0, s1 = 0.0, s2 = 0.0, s3 = 0.0;
        for (int k = 0; k < DD; k += 4) {
            s0 += Us[rr][k+0] * Xn[(k+0)*DD + j];
            s1 += Us[rr][k+1] * Xn[(k+1)*DD + j];
            s2 += Us[rr][k+2] * Xn[(k+2)*DD + j];
            s3 += Us[rr][k+3] * Xn[(k+3)*DD + j];
        }
        double v = 2.0 * Xs[rr][j] - ((s0 + s1) + (s2 + s3));
        g_NX[sel ^ 1][(i0 + rr)*DD + j] = v;
        if (emit) g_Sf[(i0 + rr)*DD + j] = (float)v;
    }
}
// W build + cq fused. Each block owns j = 2b, 2b+1 completely (128 k each).
// cq re-summed serially ascending-k by one thread per j: BIT-IDENTICAL to the
// proven k_prepcq arithmetic (cq rounding participates in tie structure).
__global__ void __launch_bounds__(256) k_prepWcq(const float* __restrict__ cb) { // <<<320, 256>>>
    __shared__ float ws[2][DD];
    int tid = threadIdx.x;
    int e = blockIdx.x*256 + tid;
    int j = e / DD, k = e % DD;
    float w;
    if (j < PP) {
        float s = 0.f;
        for (int l = 0; l < DD; l++) s = fmaf(g_Sf[l*DD+k], cb[j*DD+l], s);
        w = s;
    } else {
        w = g_Sf[(j - PP)*DD + k];
    }
    g_W[k*WC + j] = w;
    g_Wh[e] = __half_as_ushort(__float2half_rn(w));
    ws[tid >> 7][k] = w;
    __syncthreads();
    if (tid < 2) {
        int jj = blockIdx.x*2 + tid;
        if (jj < PP) {
            float s = 0.f;
            for (int kk = 0; kk < DD; kk++) s = fmaf(cb[jj*DD+kk], ws[tid][kk], s);
            g_cq[jj] = s;
        }
    }
}

// ---------------- main HMMA kernel (UNCHANGED from R12) ----------------
#define AP 272
#define A_HI   0
#define BBUF   34816
#define CQS    (BBUF + 2*17408)
#define XQS    (CQS + 256)
#define XQR    (XQS + 4096)
#define BJFs   (XQR + 512)
#define SMEM_TOT (BJFs + 512)
#define BVS    (BBUF)
#define BJS    (BBUF + 4096)
#define V2S    (BBUF + 8192)

__global__ void __launch_bounds__(256, 3) k_main(const float* __restrict__ X,
                                                 const float* __restrict__ CB,
                                                 float* __restrict__ out,
                                                 int n) {
    extern __shared__ char smem[];
    uint32_t sb = smem_u32(smem);
    int tid = threadIdx.x, lane = tid & 31, wid = tid >> 5;
    int wm = wid & 3, wn = wid >> 2;
    int blockRow = blockIdx.x * 128;

    {
        #pragma unroll
        for (int i = 0; i < 4; i++) {
            int idx = tid + 256*i;
            int row = idx >> 4, seg = idx & 15;
            cp16(sb + BBUF + row*AP + seg*16, g_Wh + (512 + row)*DD + seg*8);
        }
        CP_COMMIT();
    }
    {
        const float4* Xg = (const float4*)(X + (size_t)blockRow * DD);
        #pragma unroll
        for (int i = 0; i < 16; i++) {
            int v = tid + 256*i;
            int r = v >> 5, c4 = v & 31;
            float4 x = Xg[v];
            uint32_t* ph = (uint32_t*)(smem + A_HI + r*AP + c4*8);
            ph[0] = (uint32_t)__half_as_ushort(__float2half_rn(x.x))
                  | ((uint32_t)__half_as_ushort(__float2half_rn(x.y)) << 16);
            ph[1] = (uint32_t)__half_as_ushort(__float2half_rn(x.z))
                  | ((uint32_t)__half_as_ushort(__float2half_rn(x.w)) << 16);
        }
    }

    uint32_t acc[2][4][2];
    float xqp[4] = {0.f, 0.f, 0.f, 0.f};
    float bv1[4] = {3.4e38f, 3.4e38f, 3.4e38f, 3.4e38f};
    float bv2[4] = {3.4e38f, 3.4e38f, 3.4e38f, 3.4e38f};
    int   bj[4]  = {0, 0, 0, 0};

    uint32_t aAddrH[2];
    #pragma unroll
    for (int mt = 0; mt < 2; mt++) {
        int row = wm*32 + mt*16 + (lane & 15);
        aAddrH[mt] = sb + A_HI + (uint32_t)row*AP + (lane >> 4)*16;
    }
    uint32_t bOff[2];
    #pragma unroll
    for (int p = 0; p < 2; p++) {
        int nrow = wn*32 + p*16 + ((lane >> 4)*8) + (lane & 7);
        bOff[p] = (uint32_t)nrow*AP + (((lane >> 3) & 1)*16);
    }

    const unsigned short* AH16 = (const unsigned short*)(smem + A_HI);

    for (int c = 0; c < 10; c++) {
        __syncthreads();
        if (c + 1 < 10) {
            int nc = c + 1;
            int jb2 = (nc < 2) ? (512 + nc*64) : (nc - 2)*64;
            int buf = nc & 1;
            #pragma unroll
            for (int i = 0; i < 4; i++) {
                int idx = tid + 256*i;
                int row = idx >> 4, seg = idx & 15;
                cp16(sb + BBUF + buf*17408 + row*AP + seg*16, g_Wh + (jb2 + row)*DD + seg*8);
            }
            CP_COMMIT();
            CP_WAIT1();
        } else {
            CP_WAIT0();
        }
        if (c >= 2 && tid < 64) ((float*)(smem + CQS))[tid] = g_cq[(c-2)*64 + tid];
        __syncthreads();

        #pragma unroll
        for (int mt = 0; mt < 2; mt++)
            #pragma unroll
            for (int nt = 0; nt < 4; nt++) { acc[mt][nt][0] = 0u; acc[mt][nt][1] = 0u; }

        uint32_t bHi = sb + BBUF + (c & 1)*17408;

        #pragma unroll
        for (int ks = 0; ks < 8; ks++) {
            uint32_t ah[2][4], bh[2][4];
            #pragma unroll
            for (int mt = 0; mt < 2; mt++)
                ldsm4(ah[mt][0], ah[mt][1], ah[mt][2], ah[mt][3], aAddrH[mt] + ks*32);
            #pragma unroll
            for (int p = 0; p < 2; p++)
                ldsm4(bh[p][0], bh[p][1], bh[p][2], bh[p][3], bHi + bOff[p] + ks*32);
            #pragma unroll
            for (int mt = 0; mt < 2; mt++)
                #pragma unroll
                for (int nt = 0; nt < 4; nt++)
                    mma_h16(acc[mt][nt], ah[mt], bh[nt>>1][(nt&1)*2], bh[nt>>1][(nt&1)*2+1]);
        }

        if (c < 2) {
            #pragma unroll
            for (int mt = 0; mt < 2; mt++)
                #pragma unroll
                for (int nt = 0; nt < 4; nt++)
                    #pragma unroll
                    for (int half = 0; half < 2; half++) {
                        float2 s2 = __half22float2(*(const __half2*)&acc[mt][nt][half]);
                        int R = wm*32 + mt*16 + (lane >> 2) + (half ? 8 : 0);
                        int q = mt*2 + half;
                        int i = c*64 + wn*32 + nt*8 + (lane & 3)*2;
                        float xh0 = __half2float(__ushort_as_half(AH16[(R*AP>>1) + i]));
                        float xh1 = __half2float(__ushort_as_half(AH16[(R*AP>>1) + i + 1]));
                        xqp[q] += s2.x * xh0 + s2.y * xh1;
                    }
            if (c == 1) {
                int slot = wn*4 + (lane & 3);
                #pragma unroll
                for (int q = 0; q < 4; q++) {
                    int row = wm*32 + (lane >> 2) + q*8;
                    ((float*)(smem + XQS))[row*8 + slot] = xqp[q];
                }
                __syncthreads();
                if (slot == 0) {
                    #pragma unroll
                    for (int q = 0; q < 4; q++) {
                        int row = wm*32 + (lane >> 2) + q*8;
                        const float* xs = (const float*)(smem + XQS) + row*8;
                        float s = 0.f;
                        #pragma unroll
                        for (int t = 0; t < 8; t++) s += xs[t];
                        ((float*)(smem + XQR))[row] = s;
                    }
                }
            }
        } else {
            const float* cqs = (const float*)(smem + CQS);
            int jbase = (c - 2) * 64;
            #pragma unroll
            for (int mt = 0; mt < 2; mt++)
                #pragma unroll
                for (int nt = 0; nt < 4; nt++)
                    #pragma unroll
                    for (int half = 0; half < 2; half++) {
                        float2 s2 = __half22float2(*(const __half2*)&acc[mt][nt][half]);
                        int q = mt*2 + half;
                        int jl = wn*32 + nt*8 + (lane & 3)*2;
                        float d0 = cqs[jl]     - 2.0f * s2.x;
                        float d1 = cqs[jl + 1] - 2.0f * s2.y;
                        if (d0 < bv1[q]) { bv2[q] = bv1[q]; bv1[q] = d0; bj[q] = jbase + jl; }
                        else if (d0 < bv2[q]) { bv2[q] = d0; }
                        if (d1 < bv1[q]) { bv2[q] = bv1[q]; bv1[q] = d1; bj[q] = jbase + jl + 1; }
                        else if (d1 < bv2[q]) { bv2[q] = d1; }
                    }
        }
    }

    __syncthreads();
    {
        int slot = wn*4 + (lane & 3);
        #pragma unroll
        for (int q = 0; q < 4; q++) {
            int row = wm*32 + (lane >> 2) + q*8;
            ((float*)(smem + BVS))[row*8 + slot] = bv1[q];
            ((int*)  (smem + BJS))[row*8 + slot] = bj[q];
            ((float*)(smem + V2S))[row*8 + slot] = bv2[q];
        }
    }
    __syncthreads();

    if (tid < 128) {
        const float* v1s = (const float*)(smem + BVS) + tid*8;
        const int*   j1s = (const int*)  (smem + BJS) + tid*8;
        const float* v2s = (const float*)(smem + V2S) + tid*8;
        float v1 = v1s[0], v2 = v2s[0]; int j1 = j1s[0];
        #pragma unroll
        for (int s = 1; s < 8; s++) {
            float a1 = v1s[s], a2 = v2s[s]; int aj = j1s[s];
            if (a1 < v1 || (a1 == v1 && aj < j1)) {
                v2 = fminf(v1, a2); v1 = a1; j1 = aj;
            } else {
                v2 = fminf(v2, a1);
            }
        }
        int row = blockRow + tid;
        g_idx[row] = j1;
        g_bestv[row] = ((const float*)(smem + XQR))[tid] + v1;
        ((int*)(smem + BJFs))[tid] = j1;
        out[(size_t)n*DD + 2 + row] = (float)j1;
        if (v2 - v1 < MARGIN) {
            int pos = atomicAdd(&g_nflag, 1);
            g_flags[pos] = row;
        }
    }
    __syncthreads();

    {
        const float4* X4g = (const float4*)(X + (size_t)blockRow * DD);
        float4* O4 = (float4*)out + (size_t)blockRow * 32;
        const int* bjf = (const int*)(smem + BJFs);
        #pragma unroll
        for (int i = 0; i < 16; i++) {
            int v = tid + 256*i;
            int r = v >> 5, c4 = v & 31;
            float4 x = X4g[v];
            float4 qq = *(const float4*)(CB + (size_t)bjf[r]*DD + c4*4);
            float4 o;
            o.x = x.x + (qq.x - x.x);
            o.y = x.y + (qq.y - x.y);
            o.z = x.z + (qq.z - x.z);
            o.w = x.w + (qq.w - x.w);
            O4[v] = o;
        }
    }
}

// ---------------- exact rescore (R2 arithmetic, UNCHANGED) ----------------
#define RMT 16
__global__ void __launch_bounds__(256) k_rescore(const float* __restrict__ X) {
    extern __shared__ float sm[];
    float* Xs  = sm;
    float* Ws  = sm + RMT*DD;
    float* cqs = Ws + DD*DD;
    int*   rws = (int*)(cqs + DD);

    int tid = threadIdx.x, tx = tid & 31, ty = tid >> 5;
    int nflag = g_nflag;

    for (int grp = blockIdx.x; grp * RMT < nflag; grp += gridDim.x) {
        __syncthreads();
        if (tid < RMT) {
            int fi = grp * RMT + tid;
            rws[tid] = (fi < nflag) ? g_flags[fi] : -1;
        }
        __syncthreads();
        {
            const float4* Xg = (const float4*)X;
            float4* Xs4 = (float4*)Xs;
            for (int v = tid; v < RMT*(DD/4); v += 256) {
                int row = rws[v >> 5];
                Xs4[v] = (row >= 0) ? Xg[(size_t)row*(DD/4) + (v & 31)]
                                    : make_float4(0.f,0.f,0.f,0.f);
            }
        }

        float xq[2], bestv[2]; int bestj[2];
        #pragma unroll
        for (int i = 0; i < 2; i++) { xq[i]=0.f; bestv[i]=3.4e38f; bestj[i]=0; }

        for (int c = 0; c < 5; c++) {
            int colbase = (c == 0) ? PP : (c - 1) * DD;
            __syncthreads();
            {
                float4* Ws4 = (float4*)Ws;
                for (int u = tid; u < DD*(DD/4); u += 256) {
                    int k = u >> 5, c4 = u & 31;
                    Ws4[u] = *(const float4*)(&g_W[k*WC + colbase + c4*4]);
                }
                if (c > 0 && tid < DD) cqs[tid] = g_cq[colbase + tid];
            }
            __syncthreads();

            float4 acc[2];
            #pragma unroll
            for (int i = 0; i < 2; i++) acc[i] = make_float4(0.f,0.f,0.f,0.f);
            const float* xr0 = Xs + ty*2*DD;
            #pragma unroll 4
            for (int k = 0; k < DD; k++) {
                float4 w = *(const float4*)(&Ws[k*DD + tx*4]);
                #pragma unroll
                for (int i = 0; i < 2; i++) {
                    float xv = xr0[i*DD + k];
                    acc[i].x = fmaf(xv, w.x, acc[i].x);
                    acc[i].y = fmaf(xv, w.y, acc[i].y);
                    acc[i].z = fmaf(xv, w.z, acc[i].z);
                    acc[i].w = fmaf(xv, w.w, acc[i].w);
                }
            }

            if (c == 0) {
                #pragma unroll
                for (int i = 0; i < 2; i++) {
                    const float* xr = xr0 + i*DD + tx*4;
                    float p = acc[i].x*xr[0] + acc[i].y*xr[1]
                            + acc[i].z*xr[2] + acc[i].w*xr[3];
                    #pragma unroll
                    for (int o = 16; o; o >>= 1) p += __shfl_xor_sync(0xffffffffu, p, o);
                    xq[i] = p;
                }
            } else {
                int jb = colbase + tx*4;
                float4 cq4 = *(const float4*)(&cqs[tx*4]);
                #pragma unroll
                for (int i = 0; i < 2; i++) {
                    float d0 = (xq[i] - 2.0f*acc[i].x) + cq4.x;
                    float d1 = (xq[i] - 2.0f*acc[i].y) + cq4.y;
                    float d2 = (xq[i] - 2.0f*acc[i].z) + cq4.z;
                    float d3 = (xq[i] - 2.0f*acc[i].w) + cq4.w;
                    if (d0 < bestv[i]) { bestv[i]=d0; bestj[i]=jb+0; }
                    if (d1 < bestv[i]) { bestv[i]=d1; bestj[i]=jb+1; }
                    if (d2 < bestv[i]) { bestv[i]=d2; bestj[i]=jb+2; }
                    if (d3 < bestv[i]) { bestv[i]=d3; bestj[i]=jb+3; }
                }
            }
        }

        #pragma unroll
        for (int i = 0; i < 2; i++) {
            float v = bestv[i]; int j = bestj[i];
            #pragma unroll
            for (int o = 16; o; o >>= 1) {
                float ov = __shfl_xor_sync(0xffffffffu, v, o);
                int   oj = __shfl_xor_sync(0xffffffffu, j, o);
                if (ov < v || (ov == v && oj < j)) { v = ov; j = oj; }
            }
            bestv[i] = v; bestj[i] = j;
        }

        if (tx == 0) {
            #pragma unroll
            for (int i = 0; i < 2; i++) {
                int row = rws[ty*2 + i];
                if (row >= 0) {
                    g_idx[row] = bestj[i];
                    g_bestv[row] = bestv[i];
                }
            }
        }
    }
}

// ---------------- fused: fixup + loss/counts + final (last block) ----------------
__global__ void __launch_bounds__(256) k_lossfinal(const float* __restrict__ X,
                                                   const float* __restrict__ CB,
                                                   float* __restrict__ out,
                                                   int n, int out_size) {   // <<<128, 256>>>
    __shared__ double shd[256];
    int bid = blockIdx.x, tid = threadIdx.x;

    // fixup flagged rows
    int nf = g_nflag;
    for (int f = bid*256 + tid; f < nf; f += 128*256) {
        int row = g_flags[f];
        int j = g_idx[row];
        out[(size_t)n*DD + 2 + row] = (float)j;
        const float4* x4 = (const float4*)(X + (size_t)row*DD);
        const float4* q4 = (const float4*)(CB + (size_t)j*DD);
        float4* o4 = (float4*)out + (size_t)row*32;
        #pragma unroll 4
        for (int c = 0; c < 32; c++) {
            float4 x = x4[c], q = q4[c], o;
            o.x = x.x + (q.x - x.x);
            o.y = x.y + (q.y - x.y);
            o.z = x.z + (q.z - x.z);
            o.w = x.w + (q.w - x.w);
            o4[c] = o;
        }
    }

    // loss partials + counts
    int base = bid * 1024;
    double s = 0.0;
    #pragma unroll
    for (int r = 0; r < 4; r++) {
        int row = base + r*256 + tid;
        s += (double)g_bestv[row];
        atomicAdd(&g_counts[g_idx[row]], 1);
    }
    shd[tid] = s;
    __syncthreads();
    for (int o = 128; o; o >>= 1) { if (tid < o) shd[tid] += shd[tid+o]; __syncthreads(); }
    if (tid == 0) g_blocksum[bid] = shd[0];

    // last block finalizes
    __shared__ int amLast;
    __threadfence();
    if (tid == 0) amLast = (atomicAdd(&g_done, 1) == 127);
    __syncthreads();
    if (!amLast) return;

    int t = tid;
    double cv0 = (double)g_counts[t], cv1 = (double)g_counts[t + 256];
    shd[t] = cv0 + cv1;
    __syncthreads();
    for (int o = 128; o; o >>= 1) { if (t < o) shd[t] += shd[t+o]; __syncthreads(); }
    double total = shd[0];
    __syncthreads();
    double p0 = cv0 / (total + 1e-8), p1 = cv1 / (total + 1e-8);
    shd[t] = -(p0 * log(p0 + 1e-8)) - (p1 * log(p1 + 1e-8));
    __syncthreads();
    for (int o = 128; o; o >>= 1) { if (t < o) shd[t] += shd[t+o]; __syncthreads(); }
    double entropy = shd[0];
    __syncthreads();
    shd[t] = (t < 128) ? g_blocksum[t] : 0.0;
    __syncthreads();
    for (int o = 128; o; o >>= 1) { if (t < o) shd[t] += shd[t+o]; __syncthreads(); }
    if (t == 0) {
        double mean = shd[0] / (double)n;
        int b2 = n * DD;
        if (b2     < out_size) out[b2]     = (float)(0.1 * mean);
        if (b2 + 1 < out_size) out[b2 + 1] = (float)(mean - 200000.0 * entropy);
    }
}

extern "C" void kernel_launch(void* const* d_in, const int* in_sizes, int n_in,
                              void* d_out, int out_size) {
    const float* X  = (const float*)d_in[0];
    const float* CB = (const float*)d_in[1];
    float* out = (float*)d_out;
    int n = in_sizes[0] / DD;
    int nblocks = n / 128;

    k_transmean<<<DD, 256>>>(CB);
    k_cov<<<2048, 256>>>();
    k_ns<<<32, 256>>>(0, 0);
    k_ns<<<32, 256>>>(1, 1);
    k_prepWcq<<<320, 256>>>(CB);

    size_t rsmem = (size_t)(RMT*DD + DD*DD + DD)*4 + RMT*4;
    static bool attr_set = false;
    if (!attr_set) {
        cudaFuncSetAttribute(k_main, cudaFuncAttributeMaxDynamicSharedMemorySize, SMEM_TOT);
        cudaFuncSetAttribute(k_rescore, cudaFuncAttributeMaxDynamicSharedMemorySize, (int)rsmem);
        attr_set = true;
    }
    k_main<<<nblocks, 256, SMEM_TOT>>>(X, CB, out, n);
    k_rescore<<<256, 256, rsmem>>>(X);
    k_lossfinal<<<128, 256>>>(X, CB, out, n, out_size);
}

// round 15
// speedup vs baseline: 1.2599x; 1.2599x over previous
#include <cuda_runtime.h>
#include <cuda_fp16.h>
#include <cstdint>
#include <math.h>

#define DD 128
#define PP 512
#define WC 640
#define NN 131072
#define MARGIN 0.5f

// ---------------- device scratch ----------------
__device__ __align__(16) float  g_cbT[DD*PP];
__device__ __align__(16) float  g_mean[DD];
__device__ __align__(16) float  g_cov[DD*DD];
__device__ __align__(16) double g_NX[2][DD*DD];
__device__ __align__(16) double g_NU[DD*DD];
__device__ __align__(16) float  g_Sf[DD*DD];
__device__ __align__(16) float  g_W[DD*WC];             // k-major W (rescore)
__device__ __align__(16) unsigned short g_Wh[WC*DD];    // j-major hi fp16
__device__ __align__(16) float  g_cq[PP];
__device__ int    g_counts[PP];
__device__ double g_blocksum[128];
__device__ int    g_idx[NN];
__device__ float  g_bestv[NN];
__device__ int    g_flags[NN];
__device__ int    g_nflag;
__device__ int    g_done;

// ---------------- helpers ----------------
__device__ __forceinline__ uint32_t smem_u32(const void* p) {
    uint32_t a;
    asm("{ .reg .u64 t; cvta.to.shared.u64 t, %1; cvt.u32.u64 %0, t; }" : "=r"(a) : "l"(p));
    return a;
}
__device__ __forceinline__ void cp16(uint32_t dst, const void* src) {
    asm volatile("cp.async.cg.shared.global [%0], [%1], 16;" :: "r"(dst), "l"(src));
}
#define CP_COMMIT() asm volatile("cp.async.commit_group;" ::: "memory")
#define CP_WAIT0()  asm volatile("cp.async.wait_group 0;" ::: "memory")
#define CP_WAIT1()  asm volatile("cp.async.wait_group 1;" ::: "memory")

__device__ __forceinline__ void ldsm4(uint32_t& r0, uint32_t& r1, uint32_t& r2, uint32_t& r3, uint32_t a) {
    asm volatile("ldmatrix.sync.aligned.m8n8.x4.shared.b16 {%0,%1,%2,%3}, [%4];"
        : "=r"(r0), "=r"(r1), "=r"(r2), "=r"(r3) : "r"(a) : "memory");
}
__device__ __forceinline__ void mma_h16(uint32_t* c, const uint32_t* a, uint32_t b0, uint32_t b1) {
    asm volatile("mma.sync.aligned.m16n8k16.row.col.f16.f16.f16.f16 "
        "{%0,%1}, {%2,%3,%4,%5}, {%6,%7}, {%0,%1};"
        : "+r"(c[0]), "+r"(c[1])
        : "r"(a[0]), "r"(a[1]), "r"(a[2]), "r"(a[3]), "r"(b0), "r"(b1));
}

// ---------------- precompute ----------------
// transpose + mean + state reset
__global__ void k_transmean(const float* __restrict__ cb) {   // <<<128, 256>>>
    __shared__ float sh[256];
    int j = blockIdx.x, t = threadIdx.x;
    float a = cb[t*DD + j], b = cb[(t + 256)*DD + j];
    g_cbT[j*PP + t] = a;
    g_cbT[j*PP + t + 256] = b;
    sh[t] = a + b;
    __syncthreads();
    for (int o = 128; o; o >>= 1) { if (t < o) sh[t] += sh[t+o]; __syncthreads(); }
    if (t == 0) g_mean[j] = sh[0] * (1.0f / (float)PP);
    if (j < 2) g_counts[j*256 + t] = 0;
    if (j == 0 && t == 0) { g_nflag = 0; g_done = 0; }
}
// cov + NS init (UNCHANGED per-output fp32 arithmetic: tie-structure sensitive)
__global__ void k_cov() {                          // <<<2048, 256>>>
    int w = (blockIdx.x*blockDim.x + threadIdx.x) >> 5;
    int lane = threadIdx.x & 31;
    int i = w >> 7, j = w & 127;
    float mi = g_mean[i], mj = g_mean[j];
    float s = 0.f;
    for (int p = lane; p < PP; p += 32)
        s = fmaf(g_cbT[i*PP+p]-mi, g_cbT[j*PP+p]-mj, s);
    #pragma unroll
    for (int o = 16; o; o >>= 1) s += __shfl_xor_sync(0xffffffffu, s, o);
    if (lane == 0) {
        s = s / (float)(PP - 1);
        if (i == j) s += 1e-3f;
        g_cov[i*DD+j] = s;
        g_NX[0][i*DD+j] = (i == j) ? 1.0 / (double)s : 0.0;
    }
}
// Tiled fp64 NS kernels (R12-proven shape: 64 blocks, 16.8us, floor-bound)
__global__ void k_gemmU_t(int sel) {               // grid(8,8) block(16,16)
    __shared__ double Xs[16][17];
    __shared__ double As[16][17];
    const double* Xn = g_NX[sel];
    int ty = threadIdx.y, tx = threadIdx.x;
    int i = blockIdx.y*16 + ty;
    int jrow = blockIdx.x*16 + ty;
    double s0 = 0.0, s1 = 0.0;
    for (int kb = 0; kb < DD; kb += 16) {
        Xs[ty][tx] = Xn[i*DD + kb + tx];
        As[ty][tx] = (double)g_cov[jrow*DD + kb + tx];
        __syncthreads();
        #pragma unroll
        for (int kk = 0; kk < 16; kk += 2) {
            s0 += Xs[ty][kk]   * As[tx][kk];
            s1 += Xs[ty][kk+1] * As[tx][kk+1];
        }
        __syncthreads();
    }
    g_NU[i*DD + blockIdx.x*16 + tx] = s0 + s1;
}
__global__ void k_nupd_t(int sel, int emit) {      // grid(8,8) block(16,16)
    __shared__ double Us[16][17];
    __shared__ double Xs[16][17];
    const double* Xn = g_NX[sel];
    int ty = threadIdx.y, tx = threadIdx.x;
    int i = blockIdx.y*16 + ty;
    int jrow = blockIdx.x*16 + ty;
    double s0 = 0.0, s1 = 0.0;
    for (int kb = 0; kb < DD; kb += 16) {
        Us[ty][tx] = g_NU[i*DD + kb + tx];
        Xs[ty][tx] = Xn[jrow*DD + kb + tx];
        __syncthreads();
        #pragma unroll
        for (int kk = 0; kk < 16; kk += 2) {
            s0 += Us[ty][kk]   * Xs[tx][kk];
            s1 += Us[ty][kk+1] * Xs[tx][kk+1];
        }
        __syncthreads();
    }
    int j = blockIdx.x*16 + tx;
    double v = 2.0 * Xn[i*DD+j] - (s0 + s1);
    g_NX[sel ^ 1][i*DD+j] = v;
    if (emit) g_Sf[i*DD+j] = (float)v;
}
// W build + cq fused (R14-validated). Block owns j = 2b, 2b+1; cq re-summed
// serially ascending-k (BIT-IDENTICAL to proven k_prepcq arithmetic).
__global__ void __launch_bounds__(256) k_prepWcq(const float* __restrict__ cb) { // <<<320, 256>>>
    __shared__ float ws[2][DD];
    int tid = threadIdx.x;
    int e = blockIdx.x*256 + tid;
    int j = e / DD, k = e % DD;
    float w;
    if (j < PP) {
        float s = 0.f;
        for (int l = 0; l < DD; l++) s = fmaf(g_Sf[l*DD+k], cb[j*DD+l], s);
        w = s;
    } else {
        w = g_Sf[(j - PP)*DD + k];
    }
    g_W[k*WC + j] = w;
    g_Wh[e] = __half_as_ushort(__float2half_rn(w));
    ws[tid >> 7][k] = w;
    __syncthreads();
    if (tid < 2) {
        int jj = blockIdx.x*2 + tid;
        if (jj < PP) {
            float s = 0.f;
            for (int kk = 0; kk < DD; kk++) s = fmaf(cb[jj*DD+kk], ws[tid][kk], s);
            g_cq[jj] = s;
        }
    }
}

// ---------------- main HMMA kernel (UNCHANGED from R12) ----------------
#define AP 272
#define A_HI   0
#define BBUF   34816
#define CQS    (BBUF + 2*17408)
#define XQS    (CQS + 256)
#define XQR    (XQS + 4096)
#define BJFs   (XQR + 512)
#define SMEM_TOT (BJFs + 512)
#define BVS    (BBUF)
#define BJS    (BBUF + 4096)
#define V2S    (BBUF + 8192)

__global__ void __launch_bounds__(256, 3) k_main(const float* __restrict__ X,
                                                 const float* __restrict__ CB,
                                                 float* __restrict__ out,
                                                 int n) {
    extern __shared__ char smem[];
    uint32_t sb = smem_u32(smem);
    int tid = threadIdx.x, lane = tid & 31, wid = tid >> 5;
    int wm = wid & 3, wn = wid >> 2;
    int blockRow = blockIdx.x * 128;

    {
        #pragma unroll
        for (int i = 0; i < 4; i++) {
            int idx = tid + 256*i;
            int row = idx >> 4, seg = idx & 15;
            cp16(sb + BBUF + row*AP + seg*16, g_Wh + (512 + row)*DD + seg*8);
        }
        CP_COMMIT();
    }
    {
        const float4* Xg = (const float4*)(X + (size_t)blockRow * DD);
        #pragma unroll
        for (int i = 0; i < 16; i++) {
            int v = tid + 256*i;
            int r = v >> 5, c4 = v & 31;
            float4 x = Xg[v];
            uint32_t* ph = (uint32_t*)(smem + A_HI + r*AP + c4*8);
            ph[0] = (uint32_t)__half_as_ushort(__float2half_rn(x.x))
                  | ((uint32_t)__half_as_ushort(__float2half_rn(x.y)) << 16);
            ph[1] = (uint32_t)__half_as_ushort(__float2half_rn(x.z))
                  | ((uint32_t)__half_as_ushort(__float2half_rn(x.w)) << 16);
        }
    }

    uint32_t acc[2][4][2];
    float xqp[4] = {0.f, 0.f, 0.f, 0.f};
    float bv1[4] = {3.4e38f, 3.4e38f, 3.4e38f, 3.4e38f};
    float bv2[4] = {3.4e38f, 3.4e38f, 3.4e38f, 3.4e38f};
    int   bj[4]  = {0, 0, 0, 0};

    uint32_t aAddrH[2];
    #pragma unroll
    for (int mt = 0; mt < 2; mt++) {
        int row = wm*32 + mt*16 + (lane & 15);
        aAddrH[mt] = sb + A_HI + (uint32_t)row*AP + (lane >> 4)*16;
    }
    uint32_t bOff[2];
    #pragma unroll
    for (int p = 0; p < 2; p++) {
        int nrow = wn*32 + p*16 + ((lane >> 4)*8) + (lane & 7);
        bOff[p] = (uint32_t)nrow*AP + (((lane >> 3) & 1)*16);
    }

    const unsigned short* AH16 = (const unsigned short*)(smem + A_HI);

    for (int c = 0; c < 10; c++) {
        __syncthreads();
        if (c + 1 < 10) {
            int nc = c + 1;
            int jb2 = (nc < 2) ? (512 + nc*64) : (nc - 2)*64;
            int buf = nc & 1;
            #pragma unroll
            for (int i = 0; i < 4; i++) {
                int idx = tid + 256*i;
                int row = idx >> 4, seg = idx & 15;
                cp16(sb + BBUF + buf*17408 + row*AP + seg*16, g_Wh + (jb2 + row)*DD + seg*8);
            }
            CP_COMMIT();
            CP_WAIT1();
        } else {
            CP_WAIT0();
        }
        if (c >= 2 && tid < 64) ((float*)(smem + CQS))[tid] = g_cq[(c-2)*64 + tid];
        __syncthreads();

        #pragma unroll
        for (int mt = 0; mt < 2; mt++)
            #pragma unroll
            for (int nt = 0; nt < 4; nt++) { acc[mt][nt][0] = 0u; acc[mt][nt][1] = 0u; }

        uint32_t bHi = sb + BBUF + (c & 1)*17408;

        #pragma unroll
        for (int ks = 0; ks < 8; ks++) {
            uint32_t ah[2][4], bh[2][4];
            #pragma unroll
            for (int mt = 0; mt < 2; mt++)
                ldsm4(ah[mt][0], ah[mt][1], ah[mt][2], ah[mt][3], aAddrH[mt] + ks*32);
            #pragma unroll
            for (int p = 0; p < 2; p++)
                ldsm4(bh[p][0], bh[p][1], bh[p][2], bh[p][3], bHi + bOff[p] + ks*32);
            #pragma unroll
            for (int mt = 0; mt < 2; mt++)
                #pragma unroll
                for (int nt = 0; nt < 4; nt++)
                    mma_h16(acc[mt][nt], ah[mt], bh[nt>>1][(nt&1)*2], bh[nt>>1][(nt&1)*2+1]);
        }

        if (c < 2) {
            #pragma unroll
            for (int mt = 0; mt < 2; mt++)
                #pragma unroll
                for (int nt = 0; nt < 4; nt++)
                    #pragma unroll
                    for (int half = 0; half < 2; half++) {
                        float2 s2 = __half22float2(*(const __half2*)&acc[mt][nt][half]);
                        int R = wm*32 + mt*16 + (lane >> 2) + (half ? 8 : 0);
                        int q = mt*2 + half;
                        int i = c*64 + wn*32 + nt*8 + (lane & 3)*2;
                        float xh0 = __half2float(__ushort_as_half(AH16[(R*AP>>1) + i]));
                        float xh1 = __half2float(__ushort_as_half(AH16[(R*AP>>1) + i + 1]));
                        xqp[q] += s2.x * xh0 + s2.y * xh1;
                    }
            if (c == 1) {
                int slot = wn*4 + (lane & 3);
                #pragma unroll
                for (int q = 0; q < 4; q++) {
                    int row = wm*32 + (lane >> 2) + q*8;
                    ((float*)(smem + XQS))[row*8 + slot] = xqp[q];
                }
                __syncthreads();
                if (slot == 0) {
                    #pragma unroll
                    for (int q = 0; q < 4; q++) {
                        int row = wm*32 + (lane >> 2) + q*8;
                        const float* xs = (const float*)(smem + XQS) + row*8;
                        float s = 0.f;
                        #pragma unroll
                        for (int t = 0; t < 8; t++) s += xs[t];
                        ((float*)(smem + XQR))[row] = s;
                    }
                }
            }
        } else {
            const float* cqs = (const float*)(smem + CQS);
            int jbase = (c - 2) * 64;
            #pragma unroll
            for (int mt = 0; mt < 2; mt++)
                #pragma unroll
                for (int nt = 0; nt < 4; nt++)
                    #pragma unroll
                    for (int half = 0; half < 2; half++) {
                        float2 s2 = __half22float2(*(const __half2*)&acc[mt][nt][half]);
                        int q = mt*2 + half;
                        int jl = wn*32 + nt*8 + (lane & 3)*2;
                        float d0 = cqs[jl]     - 2.0f * s2.x;
                        float d1 = cqs[jl + 1] - 2.0f * s2.y;
                        if (d0 < bv1[q]) { bv2[q] = bv1[q]; bv1[q] = d0; bj[q] = jbase + jl; }
                        else if (d0 < bv2[q]) { bv2[q] = d0; }
                        if (d1 < bv1[q]) { bv2[q] = bv1[q]; bv1[q] = d1; bj[q] = jbase + jl + 1; }
                        else if (d1 < bv2[q]) { bv2[q] = d1; }
                    }
        }
    }

    __syncthreads();
    {
        int slot = wn*4 + (lane & 3);
        #pragma unroll
        for (int q = 0; q < 4; q++) {
            int row = wm*32 + (lane >> 2) + q*8;
            ((float*)(smem + BVS))[row*8 + slot] = bv1[q];
            ((int*)  (smem + BJS))[row*8 + slot] = bj[q];
            ((float*)(smem + V2S))[row*8 + slot] = bv2[q];
        }
    }
    __syncthreads();

    if (tid < 128) {
        const float* v1s = (const float*)(smem + BVS) + tid*8;
        const int*   j1s = (const int*)  (smem + BJS) + tid*8;
        const float* v2s = (const float*)(smem + V2S) + tid*8;
        float v1 = v1s[0], v2 = v2s[0]; int j1 = j1s[0];
        #pragma unroll
        for (int s = 1; s < 8; s++) {
            float a1 = v1s[s], a2 = v2s[s]; int aj = j1s[s];
            if (a1 < v1 || (a1 == v1 && aj < j1)) {
                v2 = fminf(v1, a2); v1 = a1; j1 = aj;
            } else {
                v2 = fminf(v2, a1);
            }
        }
        int row = blockRow + tid;
        g_idx[row] = j1;
        g_bestv[row] = ((const float*)(smem + XQR))[tid] + v1;
        ((int*)(smem + BJFs))[tid] = j1;
        out[(size_t)n*DD + 2 + row] = (float)j1;
        if (v2 - v1 < MARGIN) {
            int pos = atomicAdd(&g_nflag, 1);
            g_flags[pos] = row;
        }
    }
    __syncthreads();

    {
        const float4* X4g = (const float4*)(X + (size_t)blockRow * DD);
        float4* O4 = (float4*)out + (size_t)blockRow * 32;
        const int* bjf = (const int*)(smem + BJFs);
        #pragma unroll
        for (int i = 0; i < 16; i++) {
            int v = tid + 256*i;
            int r = v >> 5, c4 = v & 31;
            float4 x = X4g[v];
            float4 qq = *(const float4*)(CB + (size_t)bjf[r]*DD + c4*4);
            float4 o;
            o.x = x.x + (qq.x - x.x);
            o.y = x.y + (qq.y - x.y);
            o.z = x.z + (qq.z - x.z);
            o.w = x.w + (qq.w - x.w);
            O4[v] = o;
        }
    }
}

// ---------------- exact rescore (R2 arithmetic, UNCHANGED) ----------------
#define RMT 16
__global__ void __launch_bounds__(256) k_rescore(const float* __restrict__ X) {
    extern __shared__ float sm[];
    float* Xs  = sm;
    float* Ws  = sm + RMT*DD;
    float* cqs = Ws + DD*DD;
    int*   rws = (int*)(cqs + DD);

    int tid = threadIdx.x, tx = tid & 31, ty = tid >> 5;
    int nflag = g_nflag;

    for (int grp = blockIdx.x; grp * RMT < nflag; grp += gridDim.x) {
        __syncthreads();
        if (tid < RMT) {
            int fi = grp * RMT + tid;
            rws[tid] = (fi < nflag) ? g_flags[fi] : -1;
        }
        __syncthreads();
        {
            const float4* Xg = (const float4*)X;
            float4* Xs4 = (float4*)Xs;
            for (int v = tid; v < RMT*(DD/4); v += 256) {
                int row = rws[v >> 5];
                Xs4[v] = (row >= 0) ? Xg[(size_t)row*(DD/4) + (v & 31)]
                                    : make_float4(0.f,0.f,0.f,0.f);
            }
        }

        float xq[2], bestv[2]; int bestj[2];
        #pragma unroll
        for (int i = 0; i < 2; i++) { xq[i]=0.f; bestv[i]=3.4e38f; bestj[i]=0; }

        for (int c = 0; c < 5; c++) {
            int colbase = (c == 0) ? PP : (c - 1) * DD;
            __syncthreads();
            {
                float4* Ws4 = (float4*)Ws;
                for (int u = tid; u < DD*(DD/4); u += 256) {
                    int k = u >> 5, c4 = u & 31;
                    Ws4[u] = *(const float4*)(&g_W[k*WC + colbase + c4*4]);
                }
                if (c > 0 && tid < DD) cqs[tid] = g_cq[colbase + tid];
            }
            __syncthreads();

            float4 acc[2];
            #pragma unroll
            for (int i = 0; i < 2; i++) acc[i] = make_float4(0.f,0.f,0.f,0.f);
            const float* xr0 = Xs + ty*2*DD;
            #pragma unroll 4
            for (int k = 0; k < DD; k++) {
                float4 w = *(const float4*)(&Ws[k*DD + tx*4]);
                #pragma unroll
                for (int i = 0; i < 2; i++) {
                    float xv = xr0[i*DD + k];
                    acc[i].x = fmaf(xv, w.x, acc[i].x);
                    acc[i].y = fmaf(xv, w.y, acc[i].y);
                    acc[i].z = fmaf(xv, w.z, acc[i].z);
                    acc[i].w = fmaf(xv, w.w, acc[i].w);
                }
            }

            if (c == 0) {
                #pragma unroll
                for (int i = 0; i < 2; i++) {
                    const float* xr = xr0 + i*DD + tx*4;
                    float p = acc[i].x*xr[0] + acc[i].y*xr[1]
                            + acc[i].z*xr[2] + acc[i].w*xr[3];
                    #pragma unroll
                    for (int o = 16; o; o >>= 1) p += __shfl_xor_sync(0xffffffffu, p, o);
                    xq[i] = p;
                }
            } else {
                int jb = colbase + tx*4;
                float4 cq4 = *(const float4*)(&cqs[tx*4]);
                #pragma unroll
                for (int i = 0; i < 2; i++) {
                    float d0 = (xq[i] - 2.0f*acc[i].x) + cq4.x;
                    float d1 = (xq[i] - 2.0f*acc[i].y) + cq4.y;
                    float d2 = (xq[i] - 2.0f*acc[i].z) + cq4.z;
                    float d3 = (xq[i] - 2.0f*acc[i].w) + cq4.w;
                    if (d0 < bestv[i]) { bestv[i]=d0; bestj[i]=jb+0; }
                    if (d1 < bestv[i]) { bestv[i]=d1; bestj[i]=jb+1; }
                    if (d2 < bestv[i]) { bestv[i]=d2; bestj[i]=jb+2; }
                    if (d3 < bestv[i]) { bestv[i]=d3; bestj[i]=jb+3; }
                }
            }
        }

        #pragma unroll
        for (int i = 0; i < 2; i++) {
            float v = bestv[i]; int j = bestj[i];
            #pragma unroll
            for (int o = 16; o; o >>= 1) {
                float ov = __shfl_xor_sync(0xffffffffu, v, o);
                int   oj = __shfl_xor_sync(0xffffffffu, j, o);
                if (ov < v || (ov == v && oj < j)) { v = ov; j = oj; }
            }
            bestv[i] = v; bestj[i] = j;
        }

        if (tx == 0) {
            #pragma unroll
            for (int i = 0; i < 2; i++) {
                int row = rws[ty*2 + i];
                if (row >= 0) {
                    g_idx[row] = bestj[i];
                    g_bestv[row] = bestv[i];
                }
            }
        }
    }
}

// ---------------- fused: fixup + loss/counts + final (R14-validated) ----------------
__global__ void __launch_bounds__(256) k_lossfinal(const float* __restrict__ X,
                                                   const float* __restrict__ CB,
                                                   float* __restrict__ out,
                                                   int n, int out_size) {   // <<<128, 256>>>
    __shared__ double shd[256];
    int bid = blockIdx.x, tid = threadIdx.x;

    int nf = g_nflag;
    for (int f = bid*256 + tid; f < nf; f += 128*256) {
        int row = g_flags[f];
        int j = g_idx[row];
        out[(size_t)n*DD + 2 + row] = (float)j;
        const float4* x4 = (const float4*)(X + (size_t)row*DD);
        const float4* q4 = (const float4*)(CB + (size_t)j*DD);
        float4* o4 = (float4*)out + (size_t)row*32;
        #pragma unroll 4
        for (int c = 0; c < 32; c++) {
            float4 x = x4[c], q = q4[c], o;
            o.x = x.x + (q.x - x.x);
            o.y = x.y + (q.y - x.y);
            o.z = x.z + (q.z - x.z);
            o.w = x.w + (q.w - x.w);
            o4[c] = o;
        }
    }

    int base = bid * 1024;
    double s = 0.0;
    #pragma unroll
    for (int r = 0; r < 4; r++) {
        int row = base + r*256 + tid;
        s += (double)g_bestv[row];
        atomicAdd(&g_counts[g_idx[row]], 1);
    }
    shd[tid] = s;
    __syncthreads();
    for (int o = 128; o; o >>= 1) { if (tid < o) shd[tid] += shd[tid+o]; __syncthreads(); }
    if (tid == 0) g_blocksum[bid] = shd[0];

    __shared__ int amLast;
    __threadfence();
    if (tid == 0) amLast = (atomicAdd(&g_done, 1) == 127);
    __syncthreads();
    if (!amLast) return;

    int t = tid;
    double cv0 = (double)g_counts[t], cv1 = (double)g_counts[t + 256];
    shd[t] = cv0 + cv1;
    __syncthreads();
    for (int o = 128; o; o >>= 1) { if (t < o) shd[t] += shd[t+o]; __syncthreads(); }
    double total = shd[0];
    __syncthreads();
    double p0 = cv0 / (total + 1e-8), p1 = cv1 / (total + 1e-8);
    shd[t] = -(p0 * log(p0 + 1e-8)) - (p1 * log(p1 + 1e-8));
    __syncthreads();
    for (int o = 128; o; o >>= 1) { if (t < o) shd[t] += shd[t+o]; __syncthreads(); }
    double entropy = shd[0];
    __syncthreads();
    shd[t] = (t < 128) ? g_blocksum[t] : 0.0;
    __syncthreads();
    for (int o = 128; o; o >>= 1) { if (t < o) shd[t] += shd[t+o]; __syncthreads(); }
    if (t == 0) {
        double mean = shd[0] / (double)n;
        int b2 = n * DD;
        if (b2     < out_size) out[b2]     = (float)(0.1 * mean);
        if (b2 + 1 < out_size) out[b2 + 1] = (float)(mean - 200000.0 * entropy);
    }
}

extern "C" void kernel_launch(void* const* d_in, const int* in_sizes, int n_in,
                              void* d_out, int out_size) {
    const float* X  = (const float*)d_in[0];
    const float* CB = (const float*)d_in[1];
    float* out = (float*)d_out;
    int n = in_sizes[0] / DD;
    int nblocks = n / 128;

    dim3 g88(8, 8), b1616(16, 16);
    k_transmean<<<DD, 256>>>(CB);
    k_cov<<<2048, 256>>>();
    for (int it = 0; it < 2; it++) {
        k_gemmU_t<<<g88, b1616>>>(it & 1);
        k_nupd_t<<<g88, b1616>>>(it & 1, it == 1);
    }
    k_prepWcq<<<320, 256>>>(CB);

    size_t rsmem = (size_t)(RMT*DD + DD*DD + DD)*4 + RMT*4;
    static bool attr_set = false;
    if (!attr_set) {
        cudaFuncSetAttribute(k_main, cudaFuncAttributeMaxDynamicSharedMemorySize, SMEM_TOT);
        cudaFuncSetAttribute(k_rescore, cudaFuncAttributeMaxDynamicSharedMemorySize, (int)rsmem);
        attr_set = true;
    }
    k_main<<<nblocks, 256, SMEM_TOT>>>(X, CB, out, n);
    k_rescore<<<256, 256, rsmem>>>(X);
    k_lossfinal<<<128, 256>>>(X, CB, out, n, out_size);
}